// round 15
// baseline (speedup 1.0000x reference)
#include <cuda_runtime.h>
#include <cuda_fp16.h>
#include <math.h>
#include <stdint.h>

#define B_  2
#define L_  2048
#define D_  2048
#define H_  16
#define DH  128
#define NEGV  (-1000000000.0f)
#define SCALE 0.08838834764831845f

// ---- fp16 GEMM config: CTA 128x128, 256 threads, 2 CTAs/SM ---------------
#define KCH 64
#define KTH (D_ / KCH)        // 32
#define RS  72                // smem row stride in halves (144B)
#define A_H2 (128 * RS)
#define STG_H2 (256 * RS)
#define STG_B2 (STG_H2 * 2)
#define GEMM_SMEM (3 * STG_B2)
// ---- attn smem (64-row q-block, reg-P): Q(64) | K(128) | V(128) | am ----
#define RSA 136               // attn row stride in halves (272B)
#define QT_H (64 * RSA)
#define KT_H (128 * RSA)
#define AT_AM ((QT_H + 2 * KT_H) * 2)
#define ATTN_SMEM (AT_AM + 512)

// ---------------- scratch (device globals; no runtime allocation) ----------
__device__ __half g_Xh[B_*L_*D_];
__device__ __half g_Qh[B_*H_*L_*DH];          // [B,H,L,Dh] fp16, rope+scale
__device__ __half g_Kh[B_*H_*L_*DH];          // [B,H,L,Dh] fp16, rope
__device__ __half g_Vh[B_*H_*DH*L_];          // [B,H,Dh,L] fp16 (transposed)
__device__ __half g_Yh[B_*L_*D_];
__device__ __half g_WT1h[3*D_*D_];            // fp16(w_qkv^T)
__device__ __half g_WT2h[D_*D_];              // fp16(w_proj^T)

// ---------------------------- helpers -------------------------------------
__device__ __forceinline__ uint32_t smem_u32(const void* p) {
    uint32_t a;
    asm("{ .reg .u64 t; cvta.to.shared.u64 t, %1; cvt.u32.u64 %0, t; }"
        : "=r"(a) : "l"(p));
    return a;
}
__device__ __forceinline__ void cp16(uint32_t s, const void* g) {
    asm volatile("cp.async.cg.shared.global [%0], [%1], 16;\n" :: "r"(s), "l"(g));
}
template<int N> __device__ __forceinline__ void cpwait() {
    asm volatile("cp.async.wait_group %0;\n" :: "n"(N));
}
__device__ __forceinline__ void mma_f16(float* c, const uint32_t* a, const uint32_t* b) {
    asm volatile(
        "mma.sync.aligned.m16n8k16.row.col.f32.f16.f16.f32 "
        "{%0,%1,%2,%3},{%4,%5,%6,%7},{%8,%9},{%0,%1,%2,%3};\n"
        : "+f"(c[0]), "+f"(c[1]), "+f"(c[2]), "+f"(c[3])
        : "r"(a[0]), "r"(a[1]), "r"(a[2]), "r"(a[3]), "r"(b[0]), "r"(b[1]));
}
__device__ __forceinline__ void ldsm4(uint32_t& r0, uint32_t& r1, uint32_t& r2,
                                      uint32_t& r3, uint32_t a) {
    asm volatile("ldmatrix.sync.aligned.m8n8.x4.shared.b16 {%0,%1,%2,%3}, [%4];"
                 : "=r"(r0), "=r"(r1), "=r"(r2), "=r"(r3) : "r"(a));
}
__device__ __forceinline__ uint32_t h2u(__half2 h) {
    return *reinterpret_cast<uint32_t*>(&h);
}

// ============ fp16 GEMM: C[128bm, 128bn] = A[.,2048] @ B^T ================
// (R12 version, measured — unchanged)
template<int EPI>
__global__ __launch_bounds__(256, 2) void k_gemm_h(const __half* __restrict__ A,
                                                   const __half* __restrict__ Bw,
                                                   float* __restrict__ out) {
    extern __shared__ __half smh[];
    const int tid = threadIdx.x, lane = tid & 31, warp = tid >> 5;
    const int wm = warp >> 2, wn = warp & 3;
    const int r = lane >> 2, qc = lane & 3;
    const int bn = blockIdx.x, bm = blockIdx.y;

    const int rT = tid >> 3, kg = tid & 7;
    const __half* srcA = A + (size_t)(bm * 128 + rT) * D_ + kg * 8;
    const __half* srcB = Bw + (size_t)(bn * 128 + rT) * D_ + kg * 8;
    const uint32_t sb = smem_u32(smh);
    const uint32_t dA = sb + rT * (RS * 2) + kg * 16;
    const uint32_t dB = sb + A_H2 * 2 + rT * (RS * 2) + kg * 16;

    const uint32_t aBase = sb + ((wm * 64 + (lane & 15)) * RS + (lane >> 4) * 8) * 2;
    const uint32_t bBase = sb + A_H2 * 2 +
        ((wn * 32 + (lane >> 4) * 8 + (lane & 7)) * RS + ((lane >> 3) & 1) * 8) * 2;

    float acc[4][4][4];
#pragma unroll
    for (int i = 0; i < 4; i++)
#pragma unroll
        for (int j = 0; j < 4; j++)
#pragma unroll
            for (int k = 0; k < 4; k++) acc[i][j][k] = 0.f;

#define ISSUE(cc)                                                             \
    { const uint32_t so_ = ((cc) % 3) * STG_B2;                               \
      const int ko_ = (cc) * KCH;                                             \
      _Pragma("unroll") for (int i_ = 0; i_ < 4; i_++)                        \
          cp16(dA + so_ + i_ * (32 * RS * 2), srcA + ko_ + (size_t)i_ * 32 * D_); \
      _Pragma("unroll") for (int i_ = 0; i_ < 4; i_++)                        \
          cp16(dB + so_ + i_ * (32 * RS * 2), srcB + ko_ + (size_t)i_ * 32 * D_); \
      asm volatile("cp.async.commit_group;\n" ::: "memory"); }

    ISSUE(0); ISSUE(1);

    for (int ct = 0; ct < KTH; ct++) {
        if (ct < KTH - 1) cpwait<1>(); else cpwait<0>();
        __syncthreads();
        if (ct + 2 < KTH) ISSUE(ct + 2);
        const uint32_t so = (ct % 3) * STG_B2;
#pragma unroll
        for (int k0 = 0; k0 < KCH; k0 += 16) {
            uint32_t af[4][4], bf[4][2];
#pragma unroll
            for (int mi = 0; mi < 4; mi++)
                ldsm4(af[mi][0], af[mi][1], af[mi][2], af[mi][3],
                      aBase + so + (mi * 16 * RS + k0) * 2);
#pragma unroll
            for (int p = 0; p < 2; p++)
                ldsm4(bf[2*p][0], bf[2*p][1], bf[2*p+1][0], bf[2*p+1][1],
                      bBase + so + (p * 16 * RS + k0) * 2);
#pragma unroll
            for (int mi = 0; mi < 4; mi++)
#pragma unroll
                for (int ni = 0; ni < 4; ni++)
                    mma_f16(acc[mi][ni], af[mi], bf[ni]);
        }
    }
#undef ISSUE

    // ---- epilogue ----
    if (EPI == 1) {
#pragma unroll
        for (int mi = 0; mi < 4; mi++)
#pragma unroll
            for (int ni = 0; ni < 4; ni++)
#pragma unroll
                for (int h = 0; h < 2; h++) {
                    int row = wm * 64 + mi * 16 + r + 8 * h;
                    int col = wn * 32 + ni * 8 + 2 * qc;
                    int m = bm * 128 + row, n = bn * 128 + col;
                    float2 v2 = { acc[mi][ni][2*h], acc[mi][ni][2*h+1] };
                    *(float2*)(out + (size_t)m * D_ + n) = v2;
                }
    } else if (bn < 32) {
        const int hh = bn & 15;
        __half* base = (bn < 16) ? g_Qh : g_Kh;
#pragma unroll
        for (int mi = 0; mi < 4; mi++)
#pragma unroll
            for (int ni = 0; ni < 4; ni++)
#pragma unroll
                for (int h = 0; h < 2; h++) {
                    int row = wm * 64 + mi * 16 + r + 8 * h;
                    int col = wn * 32 + ni * 8 + 2 * qc;
                    int m = bm * 128 + row;
                    int bb = m >> 11, l = m & 2047;
                    __half2 hv = __floats2half2_rn(acc[mi][ni][2*h], acc[mi][ni][2*h+1]);
                    *(__half2*)(base + (((size_t)bb * H_ + hh) * L_ + l) * DH + col) = hv;
                }
    } else {
        __syncthreads();
#pragma unroll
        for (int mi = 0; mi < 4; mi++)
#pragma unroll
            for (int ni = 0; ni < 4; ni++)
#pragma unroll
                for (int rg = 0; rg < 4; rg++) {
                    int row = wm * 64 + mi * 16 + r + ((rg >> 1) ? 8 : 0);
                    int col = wn * 32 + ni * 8 + 2 * qc + (rg & 1);
                    smh[col * 136 + row] = __float2half_rn(acc[mi][ni][rg]);
                }
        __syncthreads();
        const int d = tid >> 1, vpart = tid & 1;
        const int hh = bn & 15;
        const int bb = bm >> 4, l0 = (bm & 15) * 128;
        const uint4* srcp = (const uint4*)(smh + d * 136 + vpart * 64);
        uint4* dstp = (uint4*)(g_Vh + (((size_t)bb * H_ + hh) * DH + d) * L_ +
                               l0 + vpart * 64);
#pragma unroll
        for (int i = 0; i < 8; i++) dstp[i] = srcp[i];
    }
}

// -------------------- x -> fp16 convert ------------------------------------
__global__ __launch_bounds__(256) void k_cvt(const float4* __restrict__ src) {
    int i = blockIdx.x * 256 + threadIdx.x;
    float4 a = src[2 * i], b = src[2 * i + 1];
    uint4 o;
    o.x = h2u(__floats2half2_rn(a.x, a.y));
    o.y = h2u(__floats2half2_rn(a.z, a.w));
    o.z = h2u(__floats2half2_rn(b.x, b.y));
    o.w = h2u(__floats2half2_rn(b.z, b.w));
    ((uint4*)g_Xh)[i] = o;
}

// ----------------- weight transpose (+ fp16 convert) -----------------------
__global__ __launch_bounds__(256) void k_transpose(const float* __restrict__ src,
                                                   __half* __restrict__ dst,
                                                   int R, int C) {
    __shared__ float t[32][33];
    int bx = blockIdx.x * 32, by = blockIdx.y * 32;
    int x = bx + threadIdx.x;
#pragma unroll
    for (int i = 0; i < 32; i += 8)
        t[threadIdx.y + i][threadIdx.x] = src[(size_t)(by + threadIdx.y + i) * C + x];
    __syncthreads();
    int x2 = by + threadIdx.x;
#pragma unroll
    for (int i = 0; i < 32; i += 8)
        dst[(size_t)(bx + threadIdx.y + i) * R + x2] =
            __float2half_rn(t[threadIdx.x][threadIdx.y + i]);
}

// ==== RoPE on Q (folds SCALE) and K, in place, fp16 in/out ================
__global__ void k_rope() {
    int idx = blockIdx.x * blockDim.x + threadIdx.x;
    int i   = idx & 63;
    int bhl = idx >> 6;
    int l   = bhl & 2047;
    float inv_freq = powf(10000.0f, -(float)(2 * i) * (1.0f / 128.0f));
    float ang = (float)l * inv_freq;
    float s, cc;
    sincosf(ang, &s, &cc);
    int base = bhl << 7;
    float q0 = __half2float(g_Qh[base + i]), q1 = __half2float(g_Qh[base + i + 64]);
    g_Qh[base + i]      = __float2half_rn((q0 * cc - q1 * s) * SCALE);
    g_Qh[base + i + 64] = __float2half_rn((q1 * cc + q0 * s) * SCALE);
    float k0 = __half2float(g_Kh[base + i]), k1 = __half2float(g_Kh[base + i + 64]);
    g_Kh[base + i]      = __float2half_rn(k0 * cc - k1 * s);
    g_Kh[base + i + 64] = __float2half_rn(k1 * cc + k0 * s);
}

// ======== fused flash attention: 64-row q-block, 4 warps x 16 rows,  =====
// ======== register-resident P, 2 CTAs/SM                             =====
__global__ __launch_bounds__(128, 2) void k_attn(const int* __restrict__ amask) {
    extern __shared__ __half smh[];
    __half* Qs = smh;
    __half* Ks = smh + QT_H;
    __half* Vs = smh + QT_H + KT_H;
    int*   am_s = (int*)((char*)smh + AT_AM);

    const int bq = 31 - blockIdx.x;       // 64-row q-block, largest first
    const int bh = blockIdx.y;
    const int bb = bh >> 4, hh = bh & 15;
    const int tid = threadIdx.x;
    const int lane = tid & 31, warp = tid >> 5;   // 4 warps, 16 rows each
    const int r = lane >> 2, qc = lane & 3;

    const uint32_t usb = smem_u32(smh);
    const uint32_t qA = usb + ((warp * 16 + (lane & 15)) * RSA + (lane >> 4) * 8) * 2;
    const uint32_t bOff = (((lane >> 4) * 8 + (lane & 7)) * RSA +
                           ((lane >> 3) & 1) * 8) * 2;
    const uint32_t kB = usb + QT_H * 2 + bOff;
    const uint32_t vB = usb + (QT_H + KT_H) * 2 + bOff;

    // --- load Q block (64 rows, 128 threads -> 8 uint4 each) ---
    const __half* Qg = g_Qh + (size_t)bh * L_ * DH + (size_t)bq * 64 * DH;
#pragma unroll
    for (int i = 0; i < 8; i++) {
        int g = i * 128 + tid;
        int row = g >> 4, kgg = g & 15;
        *(uint4*)&Qs[row * RSA + kgg * 8] = *(const uint4*)(Qg + row * DH + kgg * 8);
    }

    float oacc[16][4];
#pragma unroll
    for (int _j = 0; _j < 16; _j++)
#pragma unroll
        for (int _k = 0; _k < 4; _k++) oacc[_j][_k] = 0.f;
    float mrow[2] = { -3.0e38f, -3.0e38f }, lrow[2] = { 0.f, 0.f };

    const int kmax = bq >> 1;
    for (int kb = 0; kb <= kmax; kb++) {
        __syncthreads();                  // prev PV done reading Ks/Vs
        const __half* Kg = g_Kh + (size_t)bh * L_ * DH + (size_t)kb * 128 * DH;
        const __half* Vg = g_Vh + (size_t)bh * DH * L_ + (size_t)kb * 128;
#pragma unroll
        for (int i = 0; i < 16; i++) {
            int g = i * 128 + tid;
            int row = g >> 4, kgg = g & 15;
            *(uint4*)&Ks[row * RSA + kgg * 8] = *(const uint4*)(Kg + row * DH + kgg * 8);
            *(uint4*)&Vs[row * RSA + kgg * 8] = *(const uint4*)(Vg + (size_t)row * L_ + kgg * 8);
        }
        am_s[tid] = amask[bb * L_ + kb * 128 + tid];
        __syncthreads();

        // --- S = Q @ K^T  (16 rows x 128 cols per warp) ---
        float sacc[16][4];
#pragma unroll
        for (int _j = 0; _j < 16; _j++)
#pragma unroll
            for (int _k = 0; _k < 4; _k++) sacc[_j][_k] = 0.f;
#pragma unroll
        for (int k0 = 0; k0 < 128; k0 += 16) {
            uint32_t af[4], bf[16][2];
            ldsm4(af[0], af[1], af[2], af[3], qA + k0 * 2);
#pragma unroll
            for (int t = 0; t < 8; t++)
                ldsm4(bf[2*t][0], bf[2*t][1], bf[2*t+1][0], bf[2*t+1][1],
                      kB + (t * 16 * RSA + k0) * 2);
#pragma unroll
            for (int ni = 0; ni < 16; ni++)
                mma_f16(sacc[ni], af, bf[ni]);
        }

        // --- mask (pad + causal on diagonal block) ---
        const bool diag = (kb == kmax);
#pragma unroll
        for (int ni = 0; ni < 16; ni++)
#pragma unroll
            for (int rg = 0; rg < 4; rg++) {
                int col = ni * 8 + 2 * qc + (rg & 1);
                bool ok = am_s[col] != 0;
                if (diag) {
                    int qr = bq * 64 + warp * 16 + r + ((rg >> 1) ? 8 : 0);
                    ok = ok && (kb * 128 + col <= qr);
                }
                if (!ok) sacc[ni][rg] = NEGV;
            }

        // --- rowmax / online softmax (all intra-warp) ---
        float mnew[2], sfac[2];
#pragma unroll
        for (int h = 0; h < 2; h++) {
            float pm = -3.0e38f;
#pragma unroll
            for (int ni = 0; ni < 16; ni++)
                pm = fmaxf(pm, fmaxf(sacc[ni][2*h], sacc[ni][2*h+1]));
            pm = fmaxf(pm, __shfl_xor_sync(0xffffffff, pm, 1));
            pm = fmaxf(pm, __shfl_xor_sync(0xffffffff, pm, 2));
            float mn = fmaxf(mrow[h], pm);
            sfac[h] = __expf(mrow[h] - mn);
            mnew[h] = mn;
            mrow[h] = mn;
        }
#pragma unroll
        for (int h = 0; h < 2; h++) {
            float ps = 0.f;
#pragma unroll
            for (int ni = 0; ni < 16; ni++) {
                float p0 = __expf(sacc[ni][2*h]     - mnew[h]);
                float p1 = __expf(sacc[ni][2*h+1] - mnew[h]);
                sacc[ni][2*h]     = p0;
                sacc[ni][2*h+1] = p1;
                ps += p0 + p1;
                oacc[ni][2*h]     *= sfac[h];
                oacc[ni][2*h+1] *= sfac[h];
            }
            ps += __shfl_xor_sync(0xffffffff, ps, 1);
            ps += __shfl_xor_sync(0xffffffff, ps, 2);
            lrow[h] = lrow[h] * sfac[h] + ps;
        }

        // --- P (registers) -> half A-fragments, O += P @ V ---
        uint32_t apv[8][4];
#pragma unroll
        for (int ks = 0; ks < 8; ks++) {
            apv[ks][0] = h2u(__floats2half2_rn(sacc[2*ks][0],   sacc[2*ks][1]));
            apv[ks][1] = h2u(__floats2half2_rn(sacc[2*ks][2],   sacc[2*ks][3]));
            apv[ks][2] = h2u(__floats2half2_rn(sacc[2*ks+1][0], sacc[2*ks+1][1]));
            apv[ks][3] = h2u(__floats2half2_rn(sacc[2*ks+1][2], sacc[2*ks+1][3]));
        }
#pragma unroll
        for (int ks = 0; ks < 8; ks++) {
            uint32_t bf[16][2];
#pragma unroll
            for (int t = 0; t < 8; t++)
                ldsm4(bf[2*t][0], bf[2*t][1], bf[2*t+1][0], bf[2*t+1][1],
                      vB + (t * 16 * RSA + ks * 16) * 2);
#pragma unroll
            for (int ni = 0; ni < 16; ni++)
                mma_f16(oacc[ni], apv[ks], bf[ni]);
        }
    }

    // --- epilogue: O /= l, write half to g_Yh ---
#pragma unroll
    for (int h = 0; h < 2; h++) {
        float inv = 1.0f / lrow[h];
        int qg = bq * 64 + warp * 16 + r + 8 * h;
#pragma unroll
        for (int ni = 0; ni < 16; ni++) {
            int col = hh * DH + ni * 8 + 2 * qc;
            *(__half2*)&g_Yh[(size_t)(bb * L_ + qg) * D_ + col] =
                __floats2half2_rn(oacc[ni][2*h] * inv, oacc[ni][2*h+1] * inv);
        }
    }
}

// ============================== launcher ==================================
extern "C" void kernel_launch(void* const* d_in, const int* in_sizes, int n_in,
                              void* d_out, int out_size) {
    const float* x      = (const float*)d_in[0];
    const int*   amask  = (const int*)d_in[1];
    const float* w_qkv  = (const float*)d_in[2];
    const float* w_proj = (const float*)d_in[3];
    float* out = (float*)d_out;

    __half* wt1; cudaGetSymbolAddress((void**)&wt1, g_WT1h);
    __half* wt2; cudaGetSymbolAddress((void**)&wt2, g_WT2h);
    __half* gx;  cudaGetSymbolAddress((void**)&gx, g_Xh);
    __half* gy;  cudaGetSymbolAddress((void**)&gy, g_Yh);

    cudaFuncSetAttribute(k_gemm_h<0>, cudaFuncAttributeMaxDynamicSharedMemorySize, GEMM_SMEM);
    cudaFuncSetAttribute(k_gemm_h<1>, cudaFuncAttributeMaxDynamicSharedMemorySize, GEMM_SMEM);
    cudaFuncSetAttribute(k_attn, cudaFuncAttributeMaxDynamicSharedMemorySize, ATTN_SMEM);

    k_cvt<<<(B_ * L_ * D_ / 8) / 256, 256>>>((const float4*)x);
    k_transpose<<<dim3(3 * D_ / 32, D_ / 32), dim3(32, 8)>>>(w_qkv, wt1, D_, 3 * D_);
    k_transpose<<<dim3(D_ / 32, D_ / 32), dim3(32, 8)>>>(w_proj, wt2, D_, D_);
    k_gemm_h<0><<<dim3(3 * D_ / 128, B_ * L_ / 128), 256, GEMM_SMEM>>>(gx, wt1, nullptr);
    k_rope<<<(B_ * H_ * L_ * 64) / 256, 256>>>();
    k_attn<<<dim3(32, 32), 128, ATTN_SMEM>>>(amask);
    k_gemm_h<1><<<dim3(D_ / 128, B_ * L_ / 128), 256, GEMM_SMEM>>>(gy, wt2, out);
}

// round 16
// speedup vs baseline: 1.0407x; 1.0407x over previous
#include <cuda_runtime.h>
#include <cuda_fp16.h>
#include <math.h>
#include <stdint.h>

#define B_  2
#define L_  2048
#define D_  2048
#define H_  16
#define DH  128
#define NEGV  (-1000000000.0f)
#define SCALE 0.08838834764831845f

// ---- fp16 GEMM config: CTA 128x128, 256 threads, 2 CTAs/SM ---------------
#define KCH 64
#define KTH (D_ / KCH)        // 32
#define RS  72                // smem row stride in halves (144B)
#define A_H2 (128 * RS)
#define STG_H2 (256 * RS)
#define STG_B2 (STG_H2 * 2)
#define GEMM_SMEM (3 * STG_B2)
// ---- attn smem (R13 layout, 64-row q-block): Q|K(=P)|V|red1|red2|am -----
#define RSA 136               // attn row stride in halves (272B)
#define QT_H (64 * RSA)
#define KT_H (128 * RSA)
#define AT_RED1 ((QT_H + 2 * KT_H) * 2)
#define AT_RED2 (AT_RED1 + 1024)
#define AT_AM   (AT_RED2 + 1024)
#define ATTN_SMEM (AT_AM + 512)

// ---------------- scratch (device globals; no runtime allocation) ----------
__device__ __half g_Xh[B_*L_*D_];
__device__ __half g_Qh[B_*H_*L_*DH];          // [B,H,L,Dh] fp16, rope+scale
__device__ __half g_Kh[B_*H_*L_*DH];          // [B,H,L,Dh] fp16, rope
__device__ __half g_Vh[B_*H_*DH*L_];          // [B,H,Dh,L] fp16 (transposed)
__device__ __half g_Yh[B_*L_*D_];
__device__ __half g_WT1h[3*D_*D_];            // fp16(w_qkv^T)
__device__ __half g_WT2h[D_*D_];              // fp16(w_proj^T)

// ---------------------------- helpers -------------------------------------
__device__ __forceinline__ uint32_t smem_u32(const void* p) {
    uint32_t a;
    asm("{ .reg .u64 t; cvta.to.shared.u64 t, %1; cvt.u32.u64 %0, t; }"
        : "=r"(a) : "l"(p));
    return a;
}
__device__ __forceinline__ void cp16(uint32_t s, const void* g) {
    asm volatile("cp.async.cg.shared.global [%0], [%1], 16;\n" :: "r"(s), "l"(g));
}
template<int N> __device__ __forceinline__ void cpwait() {
    asm volatile("cp.async.wait_group %0;\n" :: "n"(N));
}
__device__ __forceinline__ void mma_f16(float* c, const uint32_t* a, const uint32_t* b) {
    asm volatile(
        "mma.sync.aligned.m16n8k16.row.col.f32.f16.f16.f32 "
        "{%0,%1,%2,%3},{%4,%5,%6,%7},{%8,%9},{%0,%1,%2,%3};\n"
        : "+f"(c[0]), "+f"(c[1]), "+f"(c[2]), "+f"(c[3])
        : "r"(a[0]), "r"(a[1]), "r"(a[2]), "r"(a[3]), "r"(b[0]), "r"(b[1]));
}
__device__ __forceinline__ void ldsm4(uint32_t& r0, uint32_t& r1, uint32_t& r2,
                                      uint32_t& r3, uint32_t a) {
    asm volatile("ldmatrix.sync.aligned.m8n8.x4.shared.b16 {%0,%1,%2,%3}, [%4];"
                 : "=r"(r0), "=r"(r1), "=r"(r2), "=r"(r3) : "r"(a));
}
__device__ __forceinline__ uint32_t h2u(__half2 h) {
    return *reinterpret_cast<uint32_t*>(&h);
}

// ============ fp16 GEMM: C[128bm, 128bn] = A[.,2048] @ B^T ================
// 256 threads = 8 warps (2m x 4n), warp tile 64x32, 2 CTAs/SM.
// EPI 0: qkv with FUSED ROPE for Q/K (f32 via smem), V transpose via smem.
// EPI 1: fp32 out.
template<int EPI>
__global__ __launch_bounds__(256, 2) void k_gemm_h(const __half* __restrict__ A,
                                                   const __half* __restrict__ Bw,
                                                   float* __restrict__ out) {
    extern __shared__ __half smh[];
    const int tid = threadIdx.x, lane = tid & 31, warp = tid >> 5;
    const int wm = warp >> 2, wn = warp & 3;
    const int r = lane >> 2, qc = lane & 3;
    const int bn = blockIdx.x, bm = blockIdx.y;

    const int rT = tid >> 3, kg = tid & 7;
    const __half* srcA = A + (size_t)(bm * 128 + rT) * D_ + kg * 8;
    const __half* srcB = Bw + (size_t)(bn * 128 + rT) * D_ + kg * 8;
    const uint32_t sb = smem_u32(smh);
    const uint32_t dA = sb + rT * (RS * 2) + kg * 16;
    const uint32_t dB = sb + A_H2 * 2 + rT * (RS * 2) + kg * 16;

    const uint32_t aBase = sb + ((wm * 64 + (lane & 15)) * RS + (lane >> 4) * 8) * 2;
    const uint32_t bBase = sb + A_H2 * 2 +
        ((wn * 32 + (lane >> 4) * 8 + (lane & 7)) * RS + ((lane >> 3) & 1) * 8) * 2;

    float acc[4][4][4];
#pragma unroll
    for (int i = 0; i < 4; i++)
#pragma unroll
        for (int j = 0; j < 4; j++)
#pragma unroll
            for (int k = 0; k < 4; k++) acc[i][j][k] = 0.f;

#define ISSUE(cc)                                                             \
    { const uint32_t so_ = ((cc) % 3) * STG_B2;                               \
      const int ko_ = (cc) * KCH;                                             \
      _Pragma("unroll") for (int i_ = 0; i_ < 4; i_++)                        \
          cp16(dA + so_ + i_ * (32 * RS * 2), srcA + ko_ + (size_t)i_ * 32 * D_); \
      _Pragma("unroll") for (int i_ = 0; i_ < 4; i_++)                        \
          cp16(dB + so_ + i_ * (32 * RS * 2), srcB + ko_ + (size_t)i_ * 32 * D_); \
      asm volatile("cp.async.commit_group;\n" ::: "memory"); }

    ISSUE(0); ISSUE(1);

    for (int ct = 0; ct < KTH; ct++) {
        if (ct < KTH - 1) cpwait<1>(); else cpwait<0>();
        __syncthreads();
        if (ct + 2 < KTH) ISSUE(ct + 2);
        const uint32_t so = (ct % 3) * STG_B2;
#pragma unroll
        for (int k0 = 0; k0 < KCH; k0 += 16) {
            uint32_t af[4][4], bf[4][2];
#pragma unroll
            for (int mi = 0; mi < 4; mi++)
                ldsm4(af[mi][0], af[mi][1], af[mi][2], af[mi][3],
                      aBase + so + (mi * 16 * RS + k0) * 2);
#pragma unroll
            for (int p = 0; p < 2; p++)
                ldsm4(bf[2*p][0], bf[2*p][1], bf[2*p+1][0], bf[2*p+1][1],
                      bBase + so + (p * 16 * RS + k0) * 2);
#pragma unroll
            for (int mi = 0; mi < 4; mi++)
#pragma unroll
                for (int ni = 0; ni < 4; ni++)
                    mma_f16(acc[mi][ni], af[mi], bf[ni]);
        }
    }
#undef ISSUE

    // ---- epilogue ----
    if (EPI == 1) {
#pragma unroll
        for (int mi = 0; mi < 4; mi++)
#pragma unroll
            for (int ni = 0; ni < 4; ni++)
#pragma unroll
                for (int h = 0; h < 2; h++) {
                    int row = wm * 64 + mi * 16 + r + 8 * h;
                    int col = wn * 32 + ni * 8 + 2 * qc;
                    int m = bm * 128 + row, n = bn * 128 + col;
                    float2 v2 = { acc[mi][ni][2*h], acc[mi][ni][2*h+1] };
                    *(float2*)(out + (size_t)m * D_ + n) = v2;
                }
    } else if (bn < 32) {
        // Q (bn 0-15) or K (bn 16-31): stage f32 in smem, apply RoPE, store.
        __syncthreads();
        float* smf = (float*)smh;             // 128 x 132 f32
#pragma unroll
        for (int mi = 0; mi < 4; mi++)
#pragma unroll
            for (int ni = 0; ni < 4; ni++)
#pragma unroll
                for (int rg = 0; rg < 4; rg++) {
                    int row = wm * 64 + mi * 16 + r + ((rg >> 1) ? 8 : 0);
                    int col = wn * 32 + ni * 8 + 2 * qc + (rg & 1);
                    smf[row * 132 + col] = acc[mi][ni][rg];
                }
        __syncthreads();
        const int hh = bn & 15;
        __half* basep = (bn < 16) ? g_Qh : g_Kh;
        const float sc = (bn < 16) ? SCALE : 1.0f;
        const int c = tid & 63;
        const float inv_freq = powf(10000.0f, -(float)(2 * c) * (1.0f / 128.0f));
#pragma unroll 4
        for (int j = 0; j < 32; j++) {
            int row = (tid >> 6) + 4 * j;
            int m = bm * 128 + row;
            int bb = m >> 11, l = m & 2047;
            float s, cc;
            sincosf((float)l * inv_freq, &s, &cc);
            float v0 = smf[row * 132 + c];
            float v1 = smf[row * 132 + c + 64];
            __half* dst = basep + (((size_t)bb * H_ + hh) * L_ + l) * DH;
            dst[c]      = __float2half_rn((v0 * cc - v1 * s) * sc);
            dst[c + 64] = __float2half_rn((v1 * cc + v0 * s) * sc);
        }
    } else {
        // V (bn 32-47): transpose via smem, 16B coalesced stores
        __syncthreads();
#pragma unroll
        for (int mi = 0; mi < 4; mi++)
#pragma unroll
            for (int ni = 0; ni < 4; ni++)
#pragma unroll
                for (int rg = 0; rg < 4; rg++) {
                    int row = wm * 64 + mi * 16 + r + ((rg >> 1) ? 8 : 0);
                    int col = wn * 32 + ni * 8 + 2 * qc + (rg & 1);
                    smh[col * 136 + row] = __float2half_rn(acc[mi][ni][rg]);
                }
        __syncthreads();
        const int d = tid >> 1, vpart = tid & 1;
        const int hh = bn & 15;
        const int bb = bm >> 4, l0 = (bm & 15) * 128;
        const uint4* srcp = (const uint4*)(smh + d * 136 + vpart * 64);
        uint4* dstp = (uint4*)(g_Vh + (((size_t)bb * H_ + hh) * DH + d) * L_ +
                               l0 + vpart * 64);
#pragma unroll
        for (int i = 0; i < 8; i++) dstp[i] = srcp[i];
    }
}

// -------------------- x -> fp16 convert ------------------------------------
__global__ __launch_bounds__(256) void k_cvt(const float4* __restrict__ src) {
    int i = blockIdx.x * 256 + threadIdx.x;
    float4 a = src[2 * i], b = src[2 * i + 1];
    uint4 o;
    o.x = h2u(__floats2half2_rn(a.x, a.y));
    o.y = h2u(__floats2half2_rn(a.z, a.w));
    o.z = h2u(__floats2half2_rn(b.x, b.y));
    o.w = h2u(__floats2half2_rn(b.z, b.w));
    ((uint4*)g_Xh)[i] = o;
}

// ----------------- weight transpose (+ fp16 convert) -----------------------
__global__ __launch_bounds__(256) void k_transpose(const float* __restrict__ src,
                                                   __half* __restrict__ dst,
                                                   int R, int C) {
    __shared__ float t[32][33];
    int bx = blockIdx.x * 32, by = blockIdx.y * 32;
    int x = bx + threadIdx.x;
#pragma unroll
    for (int i = 0; i < 32; i += 8)
        t[threadIdx.y + i][threadIdx.x] = src[(size_t)(by + threadIdx.y + i) * C + x];
    __syncthreads();
    int x2 = by + threadIdx.x;
#pragma unroll
    for (int i = 0; i < 32; i += 8)
        dst[(size_t)(bx + threadIdx.y + i) * R + x2] =
            __float2half_rn(t[threadIdx.x][threadIdx.y + i]);
}

// ======== fused flash attention: 64-row q-block, 2 CTAs/SM (R13) ==========
__global__ __launch_bounds__(256, 2) void k_attn(const int* __restrict__ amask) {
    extern __shared__ __half smh[];
    __half* Qs = smh;
    __half* Ks = smh + QT_H;              // reused as Ps (rows 0..63)
    __half* Vs = smh + QT_H + KT_H;
    float* red1 = (float*)((char*)smh + AT_RED1);
    float* red2 = (float*)((char*)smh + AT_RED2);
    int*   am_s = (int*)((char*)smh + AT_AM);

    const int bq = 31 - blockIdx.x;       // 64-row q-block, largest first
    const int bh = blockIdx.y;
    const int bb = bh >> 4, hh = bh & 15;
    const int tid = threadIdx.x;
    const int lane = tid & 31, warp = tid >> 5;
    const int wm = warp >> 2, wn = warp & 3;
    const int r = lane >> 2, qc = lane & 3;

    const uint32_t usb = smem_u32(smh);
    const uint32_t aOff = ((wm * 32 + (lane & 15)) * RSA + (lane >> 4) * 8) * 2;
    const uint32_t bOff = ((wn * 32 + (lane >> 4) * 8 + (lane & 7)) * RSA +
                           ((lane >> 3) & 1) * 8) * 2;
    const uint32_t qA = usb + aOff;
    const uint32_t kB = usb + QT_H * 2 + bOff;
    const uint32_t pA = usb + QT_H * 2 + aOff;
    const uint32_t vB = usb + (QT_H + KT_H) * 2 + bOff;

    // --- load Q block (64 rows) ---
    const __half* Qg = g_Qh + (size_t)bh * L_ * DH + (size_t)bq * 64 * DH;
#pragma unroll
    for (int i = 0; i < 4; i++) {
        int g = i * 256 + tid;
        int row = g >> 4, kgg = g & 15;
        *(uint4*)&Qs[row * RSA + kgg * 8] = *(const uint4*)(Qg + row * DH + kgg * 8);
    }

    float oacc[2][4][4];
#pragma unroll
    for (int _i = 0; _i < 2; _i++)
#pragma unroll
        for (int _j = 0; _j < 4; _j++)
#pragma unroll
            for (int _k = 0; _k < 4; _k++) oacc[_i][_j][_k] = 0.f;
    float mrow[2][2], lrow[2][2];
#pragma unroll
    for (int mi = 0; mi < 2; mi++)
#pragma unroll
        for (int h = 0; h < 2; h++) { mrow[mi][h] = -3.0e38f; lrow[mi][h] = 0.f; }

    const int kmax = bq >> 1;
    for (int kb = 0; kb <= kmax; kb++) {
        __syncthreads();
        const __half* Kg = g_Kh + (size_t)bh * L_ * DH + (size_t)kb * 128 * DH;
        const __half* Vg = g_Vh + (size_t)bh * DH * L_ + (size_t)kb * 128;
#pragma unroll
        for (int i = 0; i < 8; i++) {
            int g = i * 256 + tid;
            int row = g >> 4, kgg = g & 15;
            *(uint4*)&Ks[row * RSA + kgg * 8] = *(const uint4*)(Kg + row * DH + kgg * 8);
            *(uint4*)&Vs[row * RSA + kgg * 8] = *(const uint4*)(Vg + (size_t)row * L_ + kgg * 8);
        }
        if (tid < 128) am_s[tid] = amask[bb * L_ + kb * 128 + tid];
        __syncthreads();

        // --- S = Q @ K^T  (64 x 128) ---
        float sacc[2][4][4];
#pragma unroll
        for (int _i = 0; _i < 2; _i++)
#pragma unroll
            for (int _j = 0; _j < 4; _j++)
#pragma unroll
                for (int _k = 0; _k < 4; _k++) sacc[_i][_j][_k] = 0.f;
#pragma unroll
        for (int k0 = 0; k0 < 128; k0 += 16) {
            uint32_t af[2][4], bf[4][2];
#pragma unroll
            for (int mi = 0; mi < 2; mi++)
                ldsm4(af[mi][0], af[mi][1], af[mi][2], af[mi][3],
                      qA + (mi * 16 * RSA + k0) * 2);
#pragma unroll
            for (int p = 0; p < 2; p++)
                ldsm4(bf[2*p][0], bf[2*p][1], bf[2*p+1][0], bf[2*p+1][1],
                      kB + (p * 16 * RSA + k0) * 2);
#pragma unroll
            for (int mi = 0; mi < 2; mi++)
#pragma unroll
                for (int ni = 0; ni < 4; ni++)
                    mma_f16(sacc[mi][ni], af[mi], bf[ni]);
        }

        // --- mask ---
        int amf[4][2];
#pragma unroll
        for (int ni = 0; ni < 4; ni++)
#pragma unroll
            for (int par = 0; par < 2; par++)
                amf[ni][par] = am_s[wn * 32 + ni * 8 + 2 * qc + par];
        const bool diag = (kb == kmax);
#pragma unroll
        for (int mi = 0; mi < 2; mi++)
#pragma unroll
            for (int ni = 0; ni < 4; ni++)
#pragma unroll
                for (int rg = 0; rg < 4; rg++) {
                    bool ok = amf[ni][rg & 1] != 0;
                    if (diag) {
                        int qr = bq * 64 + wm * 32 + mi * 16 + r + ((rg >> 1) ? 8 : 0);
                        int kc2 = kb * 128 + wn * 32 + ni * 8 + 2 * qc + (rg & 1);
                        ok = ok && (kc2 <= qr);
                    }
                    if (!ok) sacc[mi][ni][rg] = NEGV;
                }

        // --- rowmax ---
#pragma unroll
        for (int mi = 0; mi < 2; mi++)
#pragma unroll
            for (int h = 0; h < 2; h++) {
                float pm = -3.0e38f;
#pragma unroll
                for (int ni = 0; ni < 4; ni++)
                    pm = fmaxf(pm, fmaxf(sacc[mi][ni][2 * h], sacc[mi][ni][2 * h + 1]));
                pm = fmaxf(pm, __shfl_xor_sync(0xffffffff, pm, 1));
                pm = fmaxf(pm, __shfl_xor_sync(0xffffffff, pm, 2));
                if (qc == 0)
                    red1[(wm * 32 + mi * 16 + r + 8 * h) * 4 + wn] = pm;
            }
        __syncthreads();

        float mnew[2][2], sfac[2][2];
#pragma unroll
        for (int mi = 0; mi < 2; mi++)
#pragma unroll
            for (int h = 0; h < 2; h++) {
                int row = wm * 32 + mi * 16 + r + 8 * h;
                float mb = fmaxf(fmaxf(red1[row * 4 + 0], red1[row * 4 + 1]),
                                 fmaxf(red1[row * 4 + 2], red1[row * 4 + 3]));
                float mn = fmaxf(mrow[mi][h], mb);
                sfac[mi][h] = __expf(mrow[mi][h] - mn);
                mnew[mi][h] = mn;
                mrow[mi][h] = mn;
            }

        // --- exp, partial sums, rescale O, store P (half) into Ks ---
#pragma unroll
        for (int mi = 0; mi < 2; mi++)
#pragma unroll
            for (int h = 0; h < 2; h++) {
                float ps = 0.f;
#pragma unroll
                for (int ni = 0; ni < 4; ni++) {
                    float p0 = __expf(sacc[mi][ni][2 * h]     - mnew[mi][h]);
                    float p1 = __expf(sacc[mi][ni][2 * h + 1] - mnew[mi][h]);
                    sacc[mi][ni][2 * h]     = p0;
                    sacc[mi][ni][2 * h + 1] = p1;
                    ps += p0 + p1;
                    oacc[mi][ni][2 * h]     *= sfac[mi][h];
                    oacc[mi][ni][2 * h + 1] *= sfac[mi][h];
                }
                ps += __shfl_xor_sync(0xffffffff, ps, 1);
                ps += __shfl_xor_sync(0xffffffff, ps, 2);
                int row = wm * 32 + mi * 16 + r + 8 * h;
                if (qc == 0) red2[row * 4 + wn] = ps;
                lrow[mi][h] *= sfac[mi][h];
#pragma unroll
                for (int ni = 0; ni < 4; ni++)
                    *(__half2*)&Ks[row * RSA + wn * 32 + ni * 8 + 2 * qc] =
                        __floats2half2_rn(sacc[mi][ni][2 * h], sacc[mi][ni][2 * h + 1]);
            }
        __syncthreads();

#pragma unroll
        for (int mi = 0; mi < 2; mi++)
#pragma unroll
            for (int h = 0; h < 2; h++) {
                int row = wm * 32 + mi * 16 + r + 8 * h;
                lrow[mi][h] += red2[row * 4 + 0] + red2[row * 4 + 1] +
                               red2[row * 4 + 2] + red2[row * 4 + 3];
            }

        // --- O += P @ V ---
#pragma unroll
        for (int k0 = 0; k0 < 128; k0 += 16) {
            uint32_t af[2][4], bf[4][2];
#pragma unroll
            for (int mi = 0; mi < 2; mi++)
                ldsm4(af[mi][0], af[mi][1], af[mi][2], af[mi][3],
                      pA + (mi * 16 * RSA + k0) * 2);
#pragma unroll
            for (int p = 0; p < 2; p++)
                ldsm4(bf[2*p][0], bf[2*p][1], bf[2*p+1][0], bf[2*p+1][1],
                      vB + (p * 16 * RSA + k0) * 2);
#pragma unroll
            for (int mi = 0; mi < 2; mi++)
#pragma unroll
                for (int ni = 0; ni < 4; ni++)
                    mma_f16(oacc[mi][ni], af[mi], bf[ni]);
        }
    }

    // --- epilogue: O /= l, write half to g_Yh ---
#pragma unroll
    for (int mi = 0; mi < 2; mi++)
#pragma unroll
        for (int h = 0; h < 2; h++) {
            float inv = 1.0f / lrow[mi][h];
            int qg = bq * 64 + wm * 32 + mi * 16 + r + 8 * h;
#pragma unroll
            for (int ni = 0; ni < 4; ni++) {
                int col = hh * DH + wn * 32 + ni * 8 + 2 * qc;
                *(__half2*)&g_Yh[(size_t)(bb * L_ + qg) * D_ + col] =
                    __floats2half2_rn(oacc[mi][ni][2 * h] * inv,
                                      oacc[mi][ni][2 * h + 1] * inv);
            }
        }
}

// ============================== launcher ==================================
extern "C" void kernel_launch(void* const* d_in, const int* in_sizes, int n_in,
                              void* d_out, int out_size) {
    const float* x      = (const float*)d_in[0];
    const int*   amask  = (const int*)d_in[1];
    const float* w_qkv  = (const float*)d_in[2];
    const float* w_proj = (const float*)d_in[3];
    float* out = (float*)d_out;

    __half* wt1; cudaGetSymbolAddress((void**)&wt1, g_WT1h);
    __half* wt2; cudaGetSymbolAddress((void**)&wt2, g_WT2h);
    __half* gx;  cudaGetSymbolAddress((void**)&gx, g_Xh);
    __half* gy;  cudaGetSymbolAddress((void**)&gy, g_Yh);

    cudaFuncSetAttribute(k_gemm_h<0>, cudaFuncAttributeMaxDynamicSharedMemorySize, GEMM_SMEM);
    cudaFuncSetAttribute(k_gemm_h<1>, cudaFuncAttributeMaxDynamicSharedMemorySize, GEMM_SMEM);
    cudaFuncSetAttribute(k_attn, cudaFuncAttributeMaxDynamicSharedMemorySize, ATTN_SMEM);

    k_cvt<<<(B_ * L_ * D_ / 8) / 256, 256>>>((const float4*)x);
    k_transpose<<<dim3(3 * D_ / 32, D_ / 32), dim3(32, 8)>>>(w_qkv, wt1, D_, 3 * D_);
    k_transpose<<<dim3(D_ / 32, D_ / 32), dim3(32, 8)>>>(w_proj, wt2, D_, D_);
    k_gemm_h<0><<<dim3(3 * D_ / 128, B_ * L_ / 128), 256, GEMM_SMEM>>>(gx, wt1, nullptr);
    k_attn<<<dim3(32, 32), 256, ATTN_SMEM>>>(amask);
    k_gemm_h<1><<<dim3(D_ / 128, B_ * L_ / 128), 256, GEMM_SMEM>>>(gy, wt2, out);
}